// round 9
// baseline (speedup 1.0000x reference)
#include <cuda_runtime.h>
#include <cuda_fp16.h>

#define EPSF 1e-6f
#define EXPERTS 64
#define S_MAX 524288
#define NB 608          // 4 CTAs/SM x 152 SMs, divisible by 4
#define NT 256

// Scratch (static device allocations)
__device__ __half2 g_e[(size_t)S_MAX * 32];      // exp(logits - rowmax) fp16, 64MB (128B/row)
__device__ float   g_r[S_MAX];                   // row scale
__device__ __align__(16) float g_c[EXPERTS];     // col scale
__device__ float   g_bpart[EXPERTS * NB];        // per-block column partials
__device__ unsigned g_tick;                      // last-block ticket (zero-init, self-reset)

__device__ __forceinline__ float2 h2f(unsigned u) {
    __half2 h = *reinterpret_cast<__half2*>(&u);
    return __half22float2(h);
}
__device__ __forceinline__ unsigned f2h2(float a, float b) {
    __half2 h = __floats2half2_rn(a, b);
    return *reinterpret_cast<unsigned*>(&h);
}
// fp32 dot of 8 stored fp16 (one uint4) with cq[8]  — R6 numerics
__device__ __forceinline__ float dot8(uint4 u, const float* cq) {
    float a = 0.f; float2 f;
    f = h2f(u.x); a = fmaf(f.x, cq[0], a); a = fmaf(f.y, cq[1], a);
    f = h2f(u.y); a = fmaf(f.x, cq[2], a); a = fmaf(f.y, cq[3], a);
    f = h2f(u.z); a = fmaf(f.x, cq[4], a); a = fmaf(f.y, cq[5], a);
    f = h2f(u.w); a = fmaf(f.x, cq[6], a); a = fmaf(f.y, cq[7], a);
    return a;
}
// b[i] += e[i] * rn for 8 fp16, fp32 accumulation — R6 numerics
__device__ __forceinline__ void acc8(uint4 u, float rn, float* b) {
    float2 f;
    f = h2f(u.x); b[0] = fmaf(f.x, rn, b[0]); b[1] = fmaf(f.y, rn, b[1]);
    f = h2f(u.y); b[2] = fmaf(f.x, rn, b[2]); b[3] = fmaf(f.y, rn, b[3]);
    f = h2f(u.z); b[4] = fmaf(f.x, rn, b[4]); b[5] = fmaf(f.y, rn, b[5]);
    f = h2f(u.w); b[6] = fmaf(f.x, rn, b[6]); b[7] = fmaf(f.y, rn, b[7]);
}

// Block tail: thread o of each octet owns cols o*8..o*8+7 (after warp fold,
// replicated across the 4 octets of the warp). Write per-block partials;
// last block reduces all partials and updates g_c (fixed order, deterministic).
__device__ __forceinline__ void tail_update(const float* b, float col_target,
                                            bool first) {
    __shared__ float sb[NT / 32][EXPERTS];
    __shared__ float sq[4][EXPERTS];
    __shared__ int   slast;
    int tid = threadIdx.x, lane = tid & 31, wid = tid >> 5;

    if (lane < 8) {
        #pragma unroll
        for (int i = 0; i < 8; i++) sb[wid][lane * 8 + i] = b[i];
    }
    __syncthreads();
    if (tid < EXPERTS) {
        float s = 0.f;
        #pragma unroll
        for (int w = 0; w < NT / 32; w++) s += sb[w][tid];
        g_bpart[tid * NB + blockIdx.x] = s;
    }
    __threadfence();
    if (tid == 0) {
        unsigned t = atomicAdd(&g_tick, 1u);
        slast = (t == NB - 1) ? 1 : 0;
    }
    __syncthreads();
    if (!slast) return;

    int col = tid & 63, qq = tid >> 6;
    float s = 0.f;
    for (int p = qq * (NB / 4); p < (qq + 1) * (NB / 4); p++)
        s += g_bpart[col * NB + p];
    sq[qq][col] = s;
    __syncthreads();
    if (tid < EXPERTS) {
        float btot = sq[0][tid] + sq[1][tid] + sq[2][tid] + sq[3][tid];
        float c = first ? 1.0f : g_c[tid];
        g_c[tid] = c * col_target / (c * btot + EPSF);
    }
    if (tid == 0) g_tick = 0;
}

// fold 8 float partials across the 4 octet-groups of the warp
#define FOLD4O(b)                                                              \
    _Pragma("unroll")                                                          \
    for (int o_ = 8; o_ < 32; o_ <<= 1)                                        \
        _Pragma("unroll")                                                      \
        for (int i_ = 0; i_ < 8; i_++)                                         \
            (b)[i_] += __shfl_xor_sync(0xFFFFFFFFu, (b)[i_], o_);

// ---------------------------------------------------------------------------
// K1: prep + Sinkhorn iteration 1 fused. Octet-split: 8 threads per row,
// thread o handles columns [o*8, o*8+8). Logits streamed (evict-first).
// ---------------------------------------------------------------------------
__global__ __launch_bounds__(NT, 4) void k_prep(const float* __restrict__ logits,
                                                int S, float col_target) {
    int tid = threadIdx.x, o = tid & 7;
    float b[8];
    #pragma unroll
    for (int i = 0; i < 8; i++) b[i] = 0.f;

    int go = (blockIdx.x * NT + tid) >> 3;   // global octet id
    int no = (NB * NT) >> 3;

    for (int row = go; row < S; row += no) {
        const float4* xp = reinterpret_cast<const float4*>(logits)
                           + (size_t)row * 16 + o * 2;
        float4 v0 = __ldcs(xp + 0), v1 = __ldcs(xp + 1);
        float mx = fmaxf(fmaxf(fmaxf(v0.x, v0.y), fmaxf(v0.z, v0.w)),
                         fmaxf(fmaxf(v1.x, v1.y), fmaxf(v1.z, v1.w)));
        mx = fmaxf(mx, __shfl_xor_sync(0xFFFFFFFFu, mx, 1));
        mx = fmaxf(mx, __shfl_xor_sync(0xFFFFFFFFu, mx, 2));
        mx = fmaxf(mx, __shfl_xor_sync(0xFFFFFFFFu, mx, 4));

        float f[8];
        f[0] = __expf(v0.x - mx); f[1] = __expf(v0.y - mx);
        f[2] = __expf(v0.z - mx); f[3] = __expf(v0.w - mx);
        f[4] = __expf(v1.x - mx); f[5] = __expf(v1.y - mx);
        f[6] = __expf(v1.z - mx); f[7] = __expf(v1.w - mx);

        float a = ((f[0] + f[1]) + (f[2] + f[3])) + ((f[4] + f[5]) + (f[6] + f[7]));
        a += __shfl_xor_sync(0xFFFFFFFFu, a, 1);
        a += __shfl_xor_sync(0xFFFFFFFFu, a, 2);
        a += __shfl_xor_sync(0xFFFFFFFFu, a, 4);

        uint4 e;
        e.x = f2h2(f[0], f[1]); e.y = f2h2(f[2], f[3]);
        e.z = f2h2(f[4], f[5]); e.w = f2h2(f[6], f[7]);
        reinterpret_cast<uint4*>(g_e)[(size_t)row * 8 + o] = e;

        float rn = __fdividef(1.0f, a + EPSF);
        if (o == 0) g_r[row] = rn;
        acc8(e, rn, b);   // from quantized values (matches iteration reads)
    }
    FOLD4O(b)
    tail_update(b, col_target, true);
}

// ---------------------------------------------------------------------------
// K2: one Sinkhorn iteration, octet-split, 4 rows per loop step (high MLP).
// fp32 dot + fp32 accumulate (exact R6 numerics).
// ---------------------------------------------------------------------------
__global__ __launch_bounds__(NT, 4) void k_iter(int S, float col_target) {
    __shared__ __align__(16) float sc[EXPERTS];
    int tid = threadIdx.x, o = tid & 7;
    if (tid < EXPERTS) sc[tid] = g_c[tid];
    __syncthreads();

    float cq[8];
    #pragma unroll
    for (int i = 0; i < 8; i++) cq[i] = sc[o * 8 + i];

    float b[8];
    #pragma unroll
    for (int i = 0; i < 8; i++) b[i] = 0.f;

    int go = (blockIdx.x * NT + tid) >> 3;
    int no = (NB * NT) >> 3;

    for (int rb = go * 4; rb < S; rb += no * 4) {
        uint4 e[4];
        #pragma unroll
        for (int r = 0; r < 4; r++)
            if (rb + r < S)
                e[r] = reinterpret_cast<const uint4*>(g_e)[(size_t)(rb + r) * 8 + o];

        float a[4];
        #pragma unroll
        for (int r = 0; r < 4; r++)
            a[r] = (rb + r < S) ? dot8(e[r], cq) : 0.f;
        #pragma unroll
        for (int r = 0; r < 4; r++) {
            a[r] += __shfl_xor_sync(0xFFFFFFFFu, a[r], 1);
            a[r] += __shfl_xor_sync(0xFFFFFFFFu, a[r], 2);
            a[r] += __shfl_xor_sync(0xFFFFFFFFu, a[r], 4);
        }
        #pragma unroll
        for (int r = 0; r < 4; r++) {
            if (rb + r >= S) break;
            float ri = g_r[rb + r];
            float rn = __fdividef(ri, fmaf(ri, a[r], EPSF));
            if (o == r) g_r[rb + r] = rn;
            acc8(e[r], rn, b);
        }
    }
    FOLD4O(b)
    tail_update(b, col_target, false);
}

// ---------------------------------------------------------------------------
// K3: final (k == 2 fast path). Octet-split; fp32 ranking from logits (ldcs).
// Output float32: [idx (S*2)] then [weights (S*2)].
// ---------------------------------------------------------------------------
__global__ __launch_bounds__(NT, 4) void k_final2(const float* __restrict__ logits,
                                                  float* __restrict__ out, int S) {
    __shared__ __align__(16) float sc[EXPERTS];
    int tid = threadIdx.x, o = tid & 7;
    if (tid < EXPERTS) sc[tid] = g_c[tid];
    __syncthreads();

    float cq[8];
    #pragma unroll
    for (int i = 0; i < 8; i++) cq[i] = sc[o * 8 + i];

    int go = (blockIdx.x * NT + tid) >> 3;
    int no = (NB * NT) >> 3;

    for (int row = go; row < S; row += no) {
        const float4* xp = reinterpret_cast<const float4*>(logits)
                           + (size_t)row * 16 + o * 2;
        float4 v0 = __ldcs(xp + 0), v1 = __ldcs(xp + 1);
        float mx = fmaxf(fmaxf(fmaxf(v0.x, v0.y), fmaxf(v0.z, v0.w)),
                         fmaxf(fmaxf(v1.x, v1.y), fmaxf(v1.z, v1.w)));
        mx = fmaxf(mx, __shfl_xor_sync(0xFFFFFFFFu, mx, 1));
        mx = fmaxf(mx, __shfl_xor_sync(0xFFFFFFFFu, mx, 2));
        mx = fmaxf(mx, __shfl_xor_sync(0xFFFFFFFFu, mx, 4));

        float u[8];
        u[0] = __expf(v0.x - mx) * cq[0]; u[1] = __expf(v0.y - mx) * cq[1];
        u[2] = __expf(v0.z - mx) * cq[2]; u[3] = __expf(v0.w - mx) * cq[3];
        u[4] = __expf(v1.x - mx) * cq[4]; u[5] = __expf(v1.y - mx) * cq[5];
        u[6] = __expf(v1.z - mx) * cq[6]; u[7] = __expf(v1.w - mx) * cq[7];

        float A = 0.f;
        float m1 = -1.f, m2 = -1.f, i1 = 0.f, i2 = 0.f;
        #pragma unroll
        for (int t = 0; t < 8; t++) {
            A += u[t];
            float jj = (float)(o * 8 + t);
            bool g1 = u[t] > m1, g2 = u[t] > m2;
            m2 = g1 ? m1 : (g2 ? u[t] : m2);
            i2 = g1 ? i1 : (g2 ? jj : i2);
            m1 = g1 ? u[t] : m1;
            i1 = g1 ? jj : i1;
        }
        A += __shfl_xor_sync(0xFFFFFFFFu, A, 1);
        A += __shfl_xor_sync(0xFFFFFFFFu, A, 2);
        A += __shfl_xor_sync(0xFFFFFFFFu, A, 4);

        // merge top-2 across the octet
        #pragma unroll
        for (int oo = 1; oo <= 4; oo <<= 1) {
            float om1 = __shfl_xor_sync(0xFFFFFFFFu, m1, oo);
            float oi1 = __shfl_xor_sync(0xFFFFFFFFu, i1, oo);
            float om2 = __shfl_xor_sync(0xFFFFFFFFu, m2, oo);
            float oi2 = __shfl_xor_sync(0xFFFFFFFFu, i2, oo);
            if (om1 > m1) {
                bool keep = (m1 >= om2);
                m2 = keep ? m1 : om2;
                i2 = keep ? i1 : oi2;
                m1 = om1; i1 = oi1;
            } else if (om1 > m2) {
                m2 = om1; i2 = oi1;
            }
        }

        if (o == 0) {
            float ri  = g_r[row];
            float t   = __fdividef(ri, fmaf(ri, A, EPSF));
            float w1  = m1 * t, w2 = m2 * t;
            float inv = __fdividef(1.0f, w1 + w2 + EPSF);
            reinterpret_cast<float2*>(out)[row] = make_float2(i1, i2);
            reinterpret_cast<float2*>(out)[(size_t)S + row] =
                make_float2(w1 * inv, w2 * inv);
        }
    }
}

// ---------------------------------------------------------------------------
// Generic fallback (k != 2): warp-per-row (known-correct R3 code)
// ---------------------------------------------------------------------------
__global__ void k_final_gen(const float* __restrict__ logits,
                            float* __restrict__ out, int S, int k, size_t out_n) {
    int lane = threadIdx.x & 31;
    int warp = (blockIdx.x * blockDim.x + threadIdx.x) >> 5;
    int nw   = (gridDim.x * blockDim.x) >> 5;
    float2 cc = ((const float2*)g_c)[lane];

    for (int row = warp; row < S; row += nw) {
        float2 x = ((const float2*)logits)[(size_t)row * 32 + lane];
        float m = fmaxf(x.x, x.y);
        #pragma unroll
        for (int o = 16; o; o >>= 1) m = fmaxf(m, __shfl_xor_sync(0xFFFFFFFFu, m, o));
        float u0 = __expf(x.x - m) * cc.x;
        float u1 = __expf(x.y - m) * cc.y;
        float A = u0 + u1;
        #pragma unroll
        for (int o = 16; o; o >>= 1) A += __shfl_xor_sync(0xFFFFFFFFu, A, o);
        float ri = g_r[row];
        float denom = ri * A + EPSF;
        float lu0 = u0, lu1 = u1;
        float vals[8]; int idxs[8];
        for (int t = 0; t < k; t++) {
            float lv; int li;
            if (lu0 >= lu1) { lv = lu0; li = 2 * lane; }
            else            { lv = lu1; li = 2 * lane + 1; }
            #pragma unroll
            for (int o = 16; o; o >>= 1) {
                float ov = __shfl_xor_sync(0xFFFFFFFFu, lv, o);
                int   oi = __shfl_xor_sync(0xFFFFFFFFu, li, o);
                if (ov > lv || (ov == lv && oi < li)) { lv = ov; li = oi; }
            }
            vals[t] = lv; idxs[t] = li;
            if (li == 2 * lane)     lu0 = -1.f;
            if (li == 2 * lane + 1) lu1 = -1.f;
        }
        if (lane == 0) {
            float v[8], vs = 0.f;
            for (int t = 0; t < k; t++) { v[t] = ri * vals[t] / denom; vs += v[t]; }
            float inv = 1.0f / (vs + EPSF);
            for (int t = 0; t < k; t++) {
                size_t pi = (size_t)row * k + t;
                size_t pw = (size_t)S * k + pi;
                if (pi < out_n) out[pi] = (float)idxs[t];
                if (pw < out_n) out[pw] = v[t] * inv;
            }
        }
    }
}

// ---------------------------------------------------------------------------
extern "C" void kernel_launch(void* const* d_in, const int* in_sizes, int n_in,
                              void* d_out, int out_size) {
    const float* logits = (const float*)d_in[0];
    float*       out    = (float*)d_out;

    int S = in_sizes[0] / EXPERTS;
    if (S > S_MAX) S = S_MAX;
    if (S < 1) S = 1;
    float col_target = (float)S / (float)EXPERTS;

    int k = (int)((size_t)out_size / (2 * (size_t)S));
    if (k < 1) k = 1;
    if (k > 8) k = 8;

    k_prep<<<NB, NT>>>(logits, S, col_target);          // includes iteration 1
    for (int it = 1; it < 10; it++)
        k_iter<<<NB, NT>>>(S, col_target);              // iterations 2..10
    if (k == 2)
        k_final2<<<NB, NT>>>(logits, out, S);
    else
        k_final_gen<<<4096, 256>>>(logits, out, S, k, (size_t)out_size);
}

// round 10
// speedup vs baseline: 1.5241x; 1.5241x over previous
#include <cuda_runtime.h>
#include <cuda_fp16.h>

#define EPSF 1e-6f
#define EXPERTS 64
#define S_MAX 524288
#define NB 456          // 3 CTAs/SM x 152 SMs, divisible by 4
#define NT 256

// Scratch (static device allocations)
__device__ __half2 g_e[(size_t)S_MAX * 32];      // exp(logits - rowmax) fp16, 64MB (128B/row)
__device__ float   g_r[S_MAX];                   // row scale
__device__ __align__(16) float g_c[EXPERTS];     // col scale
__device__ float   g_bpart[EXPERTS * NB];        // per-block column partials
__device__ unsigned g_tick;                      // last-block ticket (zero-init, self-reset)

__device__ __forceinline__ float2 h2f(unsigned u) {
    __half2 h = *reinterpret_cast<__half2*>(&u);
    return __half22float2(h);
}
__device__ __forceinline__ unsigned f2h2(float a, float b) {
    __half2 h = __floats2half2_rn(a, b);
    return *reinterpret_cast<unsigned*>(&h);
}
// fp32 dot of 16 stored fp16 (two uint4) with cq[16] — R6 numerics
__device__ __forceinline__ float dot16(uint4 u0, uint4 u1, const float* cq) {
    float a = 0.f; float2 f;
    f = h2f(u0.x); a = fmaf(f.x, cq[0], a);  a = fmaf(f.y, cq[1], a);
    f = h2f(u0.y); a = fmaf(f.x, cq[2], a);  a = fmaf(f.y, cq[3], a);
    f = h2f(u0.z); a = fmaf(f.x, cq[4], a);  a = fmaf(f.y, cq[5], a);
    f = h2f(u0.w); a = fmaf(f.x, cq[6], a);  a = fmaf(f.y, cq[7], a);
    f = h2f(u1.x); a = fmaf(f.x, cq[8], a);  a = fmaf(f.y, cq[9], a);
    f = h2f(u1.y); a = fmaf(f.x, cq[10], a); a = fmaf(f.y, cq[11], a);
    f = h2f(u1.z); a = fmaf(f.x, cq[12], a); a = fmaf(f.y, cq[13], a);
    f = h2f(u1.w); a = fmaf(f.x, cq[14], a); a = fmaf(f.y, cq[15], a);
    return a;
}
// b[i] += e[i] * rn for 16 fp16, fp32 accumulation — R6 numerics
__device__ __forceinline__ void acc16(uint4 u0, uint4 u1, float rn, float* b) {
    float2 f;
    f = h2f(u0.x); b[0]  = fmaf(f.x, rn, b[0]);  b[1]  = fmaf(f.y, rn, b[1]);
    f = h2f(u0.y); b[2]  = fmaf(f.x, rn, b[2]);  b[3]  = fmaf(f.y, rn, b[3]);
    f = h2f(u0.z); b[4]  = fmaf(f.x, rn, b[4]);  b[5]  = fmaf(f.y, rn, b[5]);
    f = h2f(u0.w); b[6]  = fmaf(f.x, rn, b[6]);  b[7]  = fmaf(f.y, rn, b[7]);
    f = h2f(u1.x); b[8]  = fmaf(f.x, rn, b[8]);  b[9]  = fmaf(f.y, rn, b[9]);
    f = h2f(u1.y); b[10] = fmaf(f.x, rn, b[10]); b[11] = fmaf(f.y, rn, b[11]);
    f = h2f(u1.z); b[12] = fmaf(f.x, rn, b[12]); b[13] = fmaf(f.y, rn, b[13]);
    f = h2f(u1.w); b[14] = fmaf(f.x, rn, b[14]); b[15] = fmaf(f.y, rn, b[15]);
}

// Block tail: combine per-thread column partials (thread q of each quad owns
// cols q*16..q*16+15, replicated across the 8 quads of the warp), write
// per-block partials, last block reduces + updates g_c.
__device__ __forceinline__ void tail_update(const float* b, float col_target,
                                            bool first) {
    __shared__ float sb[NT / 32][EXPERTS];
    __shared__ float sq[4][EXPERTS];
    __shared__ int   slast;
    int tid = threadIdx.x, lane = tid & 31, wid = tid >> 5;

    if (lane < 4) {
        #pragma unroll
        for (int i = 0; i < 16; i++) sb[wid][lane * 16 + i] = b[i];
    }
    __syncthreads();
    if (tid < EXPERTS) {
        float s = 0.f;
        #pragma unroll
        for (int w = 0; w < NT / 32; w++) s += sb[w][tid];
        g_bpart[tid * NB + blockIdx.x] = s;
    }
    __threadfence();
    if (tid == 0) {
        unsigned t = atomicAdd(&g_tick, 1u);
        slast = (t == NB - 1) ? 1 : 0;
    }
    __syncthreads();
    if (!slast) return;

    int col = tid & 63, qq = tid >> 6;
    float s = 0.f;
    for (int p = qq * (NB / 4); p < (qq + 1) * (NB / 4); p++)
        s += g_bpart[col * NB + p];
    sq[qq][col] = s;
    __syncthreads();
    if (tid < EXPERTS) {
        float btot = sq[0][tid] + sq[1][tid] + sq[2][tid] + sq[3][tid];
        float c = first ? 1.0f : g_c[tid];
        g_c[tid] = c * col_target / (c * btot + EPSF);
    }
    if (tid == 0) g_tick = 0;
}

// fold 16 float partials (cols q*16..q*16+15) across the 8 quads of the warp
#define FOLD8Q(b)                                                              \
    _Pragma("unroll")                                                          \
    for (int o_ = 4; o_ < 32; o_ <<= 1)                                        \
        _Pragma("unroll")                                                      \
        for (int i_ = 0; i_ < 16; i_++)                                        \
            (b)[i_] += __shfl_xor_sync(0xFFFFFFFFu, (b)[i_], o_);

// ---------------------------------------------------------------------------
// K1: prep + Sinkhorn iteration 1 fused. Quad-split: 4 threads per row,
// thread q handles columns [q*16, q*16+16). Logits streamed (evict-first).
// ---------------------------------------------------------------------------
__global__ __launch_bounds__(NT, 3) void k_prep(const float* __restrict__ logits,
                                                int S, float col_target) {
    int tid = threadIdx.x, lane = tid & 31, q = lane & 3;
    float b[16];
    #pragma unroll
    for (int i = 0; i < 16; i++) b[i] = 0.f;

    int gq = (blockIdx.x * NT + tid) >> 2;   // global quad id
    int nq = (NB * NT) >> 2;

    for (int row = gq; row < S; row += nq) {
        const float4* xp = reinterpret_cast<const float4*>(logits)
                           + (size_t)row * 16 + q * 4;
        float4 v0 = __ldcs(xp + 0), v1 = __ldcs(xp + 1);
        float4 v2 = __ldcs(xp + 2), v3 = __ldcs(xp + 3);
        float mx = fmaxf(fmaxf(fmaxf(v0.x, v0.y), fmaxf(v0.z, v0.w)),
                         fmaxf(fmaxf(v1.x, v1.y), fmaxf(v1.z, v1.w)));
        mx = fmaxf(mx, fmaxf(fmaxf(v2.x, v2.y), fmaxf(v2.z, v2.w)));
        mx = fmaxf(mx, fmaxf(fmaxf(v3.x, v3.y), fmaxf(v3.z, v3.w)));
        mx = fmaxf(mx, __shfl_xor_sync(0xFFFFFFFFu, mx, 1));
        mx = fmaxf(mx, __shfl_xor_sync(0xFFFFFFFFu, mx, 2));

        float f[16];
        f[0]  = __expf(v0.x - mx); f[1]  = __expf(v0.y - mx);
        f[2]  = __expf(v0.z - mx); f[3]  = __expf(v0.w - mx);
        f[4]  = __expf(v1.x - mx); f[5]  = __expf(v1.y - mx);
        f[6]  = __expf(v1.z - mx); f[7]  = __expf(v1.w - mx);
        f[8]  = __expf(v2.x - mx); f[9]  = __expf(v2.y - mx);
        f[10] = __expf(v2.z - mx); f[11] = __expf(v2.w - mx);
        f[12] = __expf(v3.x - mx); f[13] = __expf(v3.y - mx);
        f[14] = __expf(v3.z - mx); f[15] = __expf(v3.w - mx);

        float a = 0.f;
        #pragma unroll
        for (int i = 0; i < 16; i++) a += f[i];
        a += __shfl_xor_sync(0xFFFFFFFFu, a, 1);
        a += __shfl_xor_sync(0xFFFFFFFFu, a, 2);

        uint4 e0, e1;
        e0.x = f2h2(f[0], f[1]);   e0.y = f2h2(f[2], f[3]);
        e0.z = f2h2(f[4], f[5]);   e0.w = f2h2(f[6], f[7]);
        e1.x = f2h2(f[8], f[9]);   e1.y = f2h2(f[10], f[11]);
        e1.z = f2h2(f[12], f[13]); e1.w = f2h2(f[14], f[15]);
        uint4* dp = reinterpret_cast<uint4*>(g_e) + (size_t)row * 8 + q * 2;
        dp[0] = e0; dp[1] = e1;

        float rn = __fdividef(1.0f, a + EPSF);
        if (q == 0) g_r[row] = rn;
        acc16(e0, e1, rn, b);   // from quantized values (matches iteration reads)
    }
    FOLD8Q(b)
    tail_update(b, col_target, true);
}

// ---------------------------------------------------------------------------
// K2: one Sinkhorn iteration, quad-split, 2 rows per step, SOFTWARE-PIPELINED:
// next step's e-tile loads are issued BEFORE the current step's shuffle
// reduction (the shfl convergence point otherwise blocks load hoisting).
// fp32 dot + fp32 accumulate (exact R6 numerics).
// ---------------------------------------------------------------------------
__global__ __launch_bounds__(NT, 3) void k_iter(int S, float col_target) {
    __shared__ __align__(16) float sc[EXPERTS];
    int tid = threadIdx.x, lane = tid & 31, q = lane & 3;
    if (tid < EXPERTS) sc[tid] = g_c[tid];
    __syncthreads();

    float cq[16];
    #pragma unroll
    for (int i = 0; i < 16; i++) cq[i] = sc[q * 16 + i];

    float b[16];
    #pragma unroll
    for (int i = 0; i < 16; i++) b[i] = 0.f;

    int gq = (blockIdx.x * NT + tid) >> 2;
    int nq = (NB * NT) >> 2;
    int stride = nq * 2;

    int rb = gq * 2;
    uint4 ca0, ca1, cb0, cb1;        // current tile (2 rows x 32B)
    float r0 = 0.f, r1 = 0.f;
    if (rb < S) {
        const uint4* ep = reinterpret_cast<const uint4*>(g_e)
                          + (size_t)rb * 8 + q * 2;
        ca0 = ep[0]; ca1 = ep[1];
        cb0 = ep[8]; cb1 = ep[9];    // S is even in practice; rb+1 < S
        r0 = g_r[rb]; r1 = g_r[rb + 1];
    }

    for (; rb < S; rb += stride) {
        // ---- prefetch next step (issued before this step's shuffles) ----
        int nb = rb + stride;
        bool hasn = nb < S;
        uint4 na0, na1, nb0, nb1;
        float nr0 = 0.f, nr1 = 0.f;
        if (hasn) {
            const uint4* np = reinterpret_cast<const uint4*>(g_e)
                              + (size_t)nb * 8 + q * 2;
            na0 = np[0]; na1 = np[1];
            nb0 = np[8]; nb1 = np[9];
            nr0 = g_r[nb]; nr1 = g_r[nb + 1];
        }

        // ---- process current step ----
        float a0 = dot16(ca0, ca1, cq);
        float a1 = dot16(cb0, cb1, cq);
        a0 += __shfl_xor_sync(0xFFFFFFFFu, a0, 1);
        a0 += __shfl_xor_sync(0xFFFFFFFFu, a0, 2);
        a1 += __shfl_xor_sync(0xFFFFFFFFu, a1, 1);
        a1 += __shfl_xor_sync(0xFFFFFFFFu, a1, 2);

        float rn0 = __fdividef(r0, fmaf(r0, a0, EPSF));
        if (q == 0) g_r[rb] = rn0;
        acc16(ca0, ca1, rn0, b);

        float rn1 = __fdividef(r1, fmaf(r1, a1, EPSF));
        if (q == 1) g_r[rb + 1] = rn1;
        acc16(cb0, cb1, rn1, b);

        // ---- rotate ----
        ca0 = na0; ca1 = na1; cb0 = nb0; cb1 = nb1;
        r0 = nr0; r1 = nr1;
    }
    FOLD8Q(b)
    tail_update(b, col_target, false);
}

// ---------------------------------------------------------------------------
// K3: final (k == 2 fast path). Quad-split; fp32 ranking from logits (ldcs).
// Output float32: [idx (S*2)] then [weights (S*2)].
// ---------------------------------------------------------------------------
__global__ __launch_bounds__(NT, 3) void k_final2(const float* __restrict__ logits,
                                                  float* __restrict__ out, int S) {
    __shared__ __align__(16) float sc[EXPERTS];
    int tid = threadIdx.x, lane = tid & 31, q = lane & 3;
    if (tid < EXPERTS) sc[tid] = g_c[tid];
    __syncthreads();

    float cq[16];
    #pragma unroll
    for (int i = 0; i < 16; i++) cq[i] = sc[q * 16 + i];

    int gq = (blockIdx.x * NT + tid) >> 2;
    int nq = (NB * NT) >> 2;

    for (int row = gq; row < S; row += nq) {
        const float4* xp = reinterpret_cast<const float4*>(logits)
                           + (size_t)row * 16 + q * 4;
        float4 v0 = __ldcs(xp + 0), v1 = __ldcs(xp + 1);
        float4 v2 = __ldcs(xp + 2), v3 = __ldcs(xp + 3);
        float mx = fmaxf(fmaxf(fmaxf(v0.x, v0.y), fmaxf(v0.z, v0.w)),
                         fmaxf(fmaxf(v1.x, v1.y), fmaxf(v1.z, v1.w)));
        mx = fmaxf(mx, fmaxf(fmaxf(v2.x, v2.y), fmaxf(v2.z, v2.w)));
        mx = fmaxf(mx, fmaxf(fmaxf(v3.x, v3.y), fmaxf(v3.z, v3.w)));
        mx = fmaxf(mx, __shfl_xor_sync(0xFFFFFFFFu, mx, 1));
        mx = fmaxf(mx, __shfl_xor_sync(0xFFFFFFFFu, mx, 2));

        float u[16];
        u[0]  = __expf(v0.x - mx) * cq[0];  u[1]  = __expf(v0.y - mx) * cq[1];
        u[2]  = __expf(v0.z - mx) * cq[2];  u[3]  = __expf(v0.w - mx) * cq[3];
        u[4]  = __expf(v1.x - mx) * cq[4];  u[5]  = __expf(v1.y - mx) * cq[5];
        u[6]  = __expf(v1.z - mx) * cq[6];  u[7]  = __expf(v1.w - mx) * cq[7];
        u[8]  = __expf(v2.x - mx) * cq[8];  u[9]  = __expf(v2.y - mx) * cq[9];
        u[10] = __expf(v2.z - mx) * cq[10]; u[11] = __expf(v2.w - mx) * cq[11];
        u[12] = __expf(v3.x - mx) * cq[12]; u[13] = __expf(v3.y - mx) * cq[13];
        u[14] = __expf(v3.z - mx) * cq[14]; u[15] = __expf(v3.w - mx) * cq[15];

        float A = 0.f;
        float m1 = -1.f, m2 = -1.f, i1 = 0.f, i2 = 0.f;
        #pragma unroll
        for (int t = 0; t < 16; t++) {
            A += u[t];
            float jj = (float)(q * 16 + t);
            bool g1 = u[t] > m1, g2 = u[t] > m2;
            m2 = g1 ? m1 : (g2 ? u[t] : m2);
            i2 = g1 ? i1 : (g2 ? jj : i2);
            m1 = g1 ? u[t] : m1;
            i1 = g1 ? jj : i1;
        }
        A += __shfl_xor_sync(0xFFFFFFFFu, A, 1);
        A += __shfl_xor_sync(0xFFFFFFFFu, A, 2);

        // merge top-2 across the quad
        #pragma unroll
        for (int o = 1; o <= 2; o <<= 1) {
            float om1 = __shfl_xor_sync(0xFFFFFFFFu, m1, o);
            float oi1 = __shfl_xor_sync(0xFFFFFFFFu, i1, o);
            float om2 = __shfl_xor_sync(0xFFFFFFFFu, m2, o);
            float oi2 = __shfl_xor_sync(0xFFFFFFFFu, i2, o);
            if (om1 > m1) {
                bool keep = (m1 >= om2);
                m2 = keep ? m1 : om2;
                i2 = keep ? i1 : oi2;
                m1 = om1; i1 = oi1;
            } else if (om1 > m2) {
                m2 = om1; i2 = oi1;
            }
        }

        if (q == 0) {
            float ri  = g_r[row];
            float t   = __fdividef(ri, fmaf(ri, A, EPSF));
            float w1  = m1 * t, w2 = m2 * t;
            float inv = __fdividef(1.0f, w1 + w2 + EPSF);
            reinterpret_cast<float2*>(out)[row] = make_float2(i1, i2);
            reinterpret_cast<float2*>(out)[(size_t)S + row] =
                make_float2(w1 * inv, w2 * inv);
        }
    }
}

// ---------------------------------------------------------------------------
// Generic fallback (k != 2): warp-per-row (known-correct R3 code)
// ---------------------------------------------------------------------------
__global__ void k_final_gen(const float* __restrict__ logits,
                            float* __restrict__ out, int S, int k, size_t out_n) {
    int lane = threadIdx.x & 31;
    int warp = (blockIdx.x * blockDim.x + threadIdx.x) >> 5;
    int nw   = (gridDim.x * blockDim.x) >> 5;
    float2 cc = ((const float2*)g_c)[lane];

    for (int row = warp; row < S; row += nw) {
        float2 x = ((const float2*)logits)[(size_t)row * 32 + lane];
        float m = fmaxf(x.x, x.y);
        #pragma unroll
        for (int o = 16; o; o >>= 1) m = fmaxf(m, __shfl_xor_sync(0xFFFFFFFFu, m, o));
        float u0 = __expf(x.x - m) * cc.x;
        float u1 = __expf(x.y - m) * cc.y;
        float A = u0 + u1;
        #pragma unroll
        for (int o = 16; o; o >>= 1) A += __shfl_xor_sync(0xFFFFFFFFu, A, o);
        float ri = g_r[row];
        float denom = ri * A + EPSF;
        float lu0 = u0, lu1 = u1;
        float vals[8]; int idxs[8];
        for (int t = 0; t < k; t++) {
            float lv; int li;
            if (lu0 >= lu1) { lv = lu0; li = 2 * lane; }
            else            { lv = lu1; li = 2 * lane + 1; }
            #pragma unroll
            for (int o = 16; o; o >>= 1) {
                float ov = __shfl_xor_sync(0xFFFFFFFFu, lv, o);
                int   oi = __shfl_xor_sync(0xFFFFFFFFu, li, o);
                if (ov > lv || (ov == lv && oi < li)) { lv = ov; li = oi; }
            }
            vals[t] = lv; idxs[t] = li;
            if (li == 2 * lane)     lu0 = -1.f;
            if (li == 2 * lane + 1) lu1 = -1.f;
        }
        if (lane == 0) {
            float v[8], vs = 0.f;
            for (int t = 0; t < k; t++) { v[t] = ri * vals[t] / denom; vs += v[t]; }
            float inv = 1.0f / (vs + EPSF);
            for (int t = 0; t < k; t++) {
                size_t pi = (size_t)row * k + t;
                size_t pw = (size_t)S * k + pi;
                if (pi < out_n) out[pi] = (float)idxs[t];
                if (pw < out_n) out[pw] = v[t] * inv;
            }
        }
    }
}

// ---------------------------------------------------------------------------
extern "C" void kernel_launch(void* const* d_in, const int* in_sizes, int n_in,
                              void* d_out, int out_size) {
    const float* logits = (const float*)d_in[0];
    float*       out    = (float*)d_out;

    int S = in_sizes[0] / EXPERTS;
    if (S > S_MAX) S = S_MAX;
    if (S < 1) S = 1;
    float col_target = (float)S / (float)EXPERTS;

    int k = (int)((size_t)out_size / (2 * (size_t)S));
    if (k < 1) k = 1;
    if (k > 8) k = 8;

    k_prep<<<NB, NT>>>(logits, S, col_target);          // includes iteration 1
    for (int it = 1; it < 10; it++)
        k_iter<<<NB, NT>>>(S, col_target);              // iterations 2..10
    if (k == 2)
        k_final2<<<NB, NT>>>(logits, out, S);
    else
        k_final_gen<<<4096, 256>>>(logits, out, S, k, (size_t)out_size);
}